// round 7
// baseline (speedup 1.0000x reference)
#include <cuda_runtime.h>
#include <cuda_bf16.h>
#include <math.h>
#include <stdint.h>

// ---------------- problem constants ----------------
#define N_ROWS 8192
#define F_IN   512
#define HID    256
#define WDIM   64

#define TMROWS 64
#define GRID_F 128
#define NT     512
#define PNT    256

// gmem weight sizes (u32 bf16-pairs)
#define NW1P  65536
#define NW2P  32768
#define NWQP  8192
#define PREP_TOTAL (NW1P + NW2P + NWQP)
#define PREP_GRID  (PREP_TOTAL / PNT)

// ---------------- smem layout (u32 units) ----------------
#define LDA 20            // A tile stride, ≡4 mod 32
#define LDE 132           // enc / Wq stride, ≡4 mod 32

#define U_A0H 0
#define U_A0L 1280
#define U_A1H 2560
#define U_A1L 3840
#define U_E   0           // sEh [64*132] = 8448 (A bufs overlay temporally)
#define U_EL  8448
#define U_B   16896       // B bufs: buf c @ U_B + c*8192 (hi|lo 4096 each); Wq reuses
#define U_C   33792
#define SMEM_U32   34432
#define SMEM_BYTES (SMEM_U32 * 4)   // 137728

// ---------------- device globals ----------------
__device__ uint32_t g_W1Thi[NW1P];
__device__ uint32_t g_W1Tlo[NW1P];
__device__ uint32_t g_W2Thi[NW2P];
__device__ uint32_t g_W2Tlo[NW2P];
__device__ uint32_t g_WqThi[NWQP];
__device__ uint32_t g_WqTlo[NWQP];
__device__ float    g_partial[GRID_F];
__device__ unsigned g_count;

// ---------------- helpers ----------------
__device__ __forceinline__ void split2(float a, float b, uint32_t& hi, uint32_t& lo) {
    __nv_bfloat16 ha = __float2bfloat16(a), hb = __float2bfloat16(b);
    float ra = a - __bfloat162float(ha), rb = b - __bfloat162float(hb);
    __nv_bfloat16 la = __float2bfloat16(ra), lb = __float2bfloat16(rb);
    hi = (uint32_t)__bfloat16_as_ushort(ha) | ((uint32_t)__bfloat16_as_ushort(hb) << 16);
    lo = (uint32_t)__bfloat16_as_ushort(la) | ((uint32_t)__bfloat16_as_ushort(lb) << 16);
}

#define MMA_BF16(acc, a, b0, b1) \
    asm volatile("mma.sync.aligned.m16n8k16.row.col.f32.bf16.bf16.f32 " \
                 "{%0,%1,%2,%3}, {%4,%5,%6,%7}, {%8,%9}, {%0,%1,%2,%3};" \
                 : "+f"((acc)[0]), "+f"((acc)[1]), "+f"((acc)[2]), "+f"((acc)[3]) \
                 : "r"((a)[0]), "r"((a)[1]), "r"((a)[2]), "r"((a)[3]), \
                   "r"(b0), "r"(b1))

#define CP16(sm_bytes, gptr) \
    asm volatile("cp.async.cg.shared.global [%0], [%1], 16;" \
                 :: "r"(sm_bytes), "l"(gptr))
#define CP_COMMIT() asm volatile("cp.async.commit_group;")
#define CP_WAIT0()  asm volatile("cp.async.wait_group 0;" ::: "memory")
#define CP_WAIT1()  asm volatile("cp.async.wait_group 1;" ::: "memory")

// ---------------- prep: weight split + transpose + pair-interleave ----------------
__global__ void __launch_bounds__(PNT)
prep_kernel(const float* __restrict__ W1, const float* __restrict__ W2,
            const float* __restrict__ Wq)
{
    int p = blockIdx.x * PNT + threadIdx.x;
    if (p == 0) g_count = 0;
    if (p < NW1P) {
        int q = p & 7, n = (p >> 3) & 255, c2 = p >> 11;
        int pp = ((q & 1) << 2) | (q >> 1);
        int kk = (c2 * 8 + pp) * 2;
        split2(W1[kk * HID + n], W1[(kk + 1) * HID + n], g_W1Thi[p], g_W1Tlo[p]);
    } else if ((p -= NW1P) < NW2P) {
        int q = p & 7, n = (p >> 3) & 255, c2 = p >> 11;
        int pp = ((q & 1) << 2) | (q >> 1);
        int kk = (c2 * 8 + pp) * 2;
        split2(W2[kk * HID + n], W2[(kk + 1) * HID + n], g_W2Thi[p], g_W2Tlo[p]);
    } else if ((p -= NW2P) < NWQP) {
        int n = p >> 7, kk = (p & 127) * 2;
        split2(Wq[kk * WDIM + n], Wq[(kk + 1) * WDIM + n], g_WqThi[p], g_WqTlo[p]);
    }
}

// ---------------- main fused kernel ----------------
__global__ void __launch_bounds__(NT, 1)
main_kernel(const float* __restrict__ X,  const float* __restrict__ b1,
            const float* __restrict__ b2, const float* __restrict__ bq,
            const float* __restrict__ Wh, const float* __restrict__ bh,
            float* __restrict__ out)
{
    extern __shared__ uint32_t S[];
    const unsigned sb4 = (unsigned)__cvta_generic_to_shared(S);

    float* sB1f = (float*)(S + U_C);
    float* sB2f = sB1f + 256;
    float* sBQf = sB2f + 256;
    float* sWHf = sBQf + 64;

    const int tid  = threadIdx.x;
    const int lane = tid & 31;
    const int warp = tid >> 5;
    const int wn   = warp & 7;          // 8 N blocks of 32 (L1/L2) / 8 (L3)
    const int wm   = warp >> 3;         // 2 M blocks of 32 rows
    const int g    = lane >> 2;
    const int kp   = lane & 3;
    const int row0 = blockIdx.x * TMROWS;
    const int mrow = wm * 32 + g;       // +mt*16, +8 variants

    const int xr = tid >> 3, xc = tid & 7;

    if (tid < 256) { sB1f[tid] = b1[tid]; sB2f[tid] = b2[tid]; }
    else if (tid < 320) { sBQf[tid - 256] = bq[tid - 256]; sWHf[tid - 256] = Wh[tid - 256]; }

    float acc[2][4][4];
#pragma unroll
    for (int mt = 0; mt < 2; ++mt)
#pragma unroll
        for (int j = 0; j < 4; ++j)
#pragma unroll
            for (int q = 0; q < 4; ++q) acc[mt][j][q] = 0.f;

    const float* xrow = X + (size_t)(row0 + xr) * F_IN + xc * 4;

    // prologue: X tile0 -> regs ; B(W1) tile0 -> buf0
    float4 xv = *(const float4*)xrow;
#pragma unroll
    for (int k = 0; k < 2; ++k) {
        int i = (tid + k * NT) * 4;
        CP16(sb4 + (U_B + i) * 4,        g_W1Thi + i);
        CP16(sb4 + (U_B + 4096 + i) * 4, g_W1Tlo + i);
    }
    CP_COMMIT();

    // ========== Layer 1: X @ W1  (16 K-tiles of 32) ==========
    for (int t = 0; t < 16; ++t) {
        const int cur = t & 1;
        const int abH = cur ? U_A1H : U_A0H;
        const int abL = cur ? U_A1L : U_A0L;
        const int bb  = U_B + cur * 8192;
        {
            uint2 H, L;
            split2(xv.x, xv.y, H.x, L.x);
            split2(xv.z, xv.w, H.y, L.y);
            *(uint2*)&S[abH + xr * LDA + xc * 2] = H;
            *(uint2*)&S[abL + xr * LDA + xc * 2] = L;
        }
        if (t < 15) {
            xv = *(const float4*)(xrow + (t + 1) * 32);
            const int nb = U_B + (1 - cur) * 8192;
#pragma unroll
            for (int k = 0; k < 2; ++k) {
                int i = (tid + k * NT) * 4;
                CP16(sb4 + (nb + i) * 4,        g_W1Thi + (t + 1) * 4096 + i);
                CP16(sb4 + (nb + 4096 + i) * 4, g_W1Tlo + (t + 1) * 4096 + i);
            }
            CP_COMMIT();
            CP_WAIT1();
        } else {
            CP_WAIT0();
        }
        __syncthreads();
#pragma unroll
        for (int ks = 0; ks < 2; ++ks) {
            const int kb = ks * 8 + kp;
            uint32_t ah[2][4], al[2][4];
#pragma unroll
            for (int mt = 0; mt < 2; ++mt) {
                int r = (mrow + mt * 16) * LDA + kb;
                ah[mt][0] = S[abH + r];                ah[mt][1] = S[abH + r + 8 * LDA];
                ah[mt][2] = S[abH + r + 4];            ah[mt][3] = S[abH + r + 8 * LDA + 4];
                al[mt][0] = S[abL + r];                al[mt][1] = S[abL + r + 8 * LDA];
                al[mt][2] = S[abL + r + 4];            al[mt][3] = S[abL + r + 8 * LDA + 4];
            }
            uint2 bhv[4], blv[4];
#pragma unroll
            for (int j = 0; j < 4; ++j) {
                int bi = bb + ks * 2048 + (wn * 32 + j * 8 + g) * 8 + 2 * kp;
                bhv[j] = *(const uint2*)&S[bi];
                blv[j] = *(const uint2*)&S[bi + 4096];
            }
            // term-major: 8 independent MMAs per pass
#pragma unroll
            for (int mt = 0; mt < 2; ++mt)
#pragma unroll
                for (int j = 0; j < 4; ++j)
                    MMA_BF16(acc[mt][j], ah[mt], bhv[j].x, bhv[j].y);
#pragma unroll
            for (int mt = 0; mt < 2; ++mt)
#pragma unroll
                for (int j = 0; j < 4; ++j)
                    MMA_BF16(acc[mt][j], ah[mt], blv[j].x, blv[j].y);
#pragma unroll
            for (int mt = 0; mt < 2; ++mt)
#pragma unroll
                for (int j = 0; j < 4; ++j)
                    MMA_BF16(acc[mt][j], al[mt], bhv[j].x, bhv[j].y);
        }
        __syncthreads();
    }

    // prefetch W2 tile0
#pragma unroll
    for (int k = 0; k < 2; ++k) {
        int i = (tid + k * NT) * 4;
        CP16(sb4 + (U_B + i) * 4,        g_W2Thi + i);
        CP16(sb4 + (U_B + 4096 + i) * 4, g_W2Tlo + i);
    }
    CP_COMMIT();

    // epilogue 1: relu+bias, split -> sE
#pragma unroll
    for (int mt = 0; mt < 2; ++mt)
#pragma unroll
        for (int j = 0; j < 4; ++j) {
            int n = wn * 32 + j * 8 + 2 * kp;
            int r = mrow + mt * 16;
            float e0 = fmaxf(acc[mt][j][0] + sB1f[n],     0.f);
            float e1 = fmaxf(acc[mt][j][1] + sB1f[n + 1], 0.f);
            float e2 = fmaxf(acc[mt][j][2] + sB1f[n],     0.f);
            float e3 = fmaxf(acc[mt][j][3] + sB1f[n + 1], 0.f);
            int p0 = r * LDE + (n >> 1), p1 = p0 + 8 * LDE;
            split2(e0, e1, S[U_E + p0],  S[U_EL + p0]);
            split2(e2, e3, S[U_E + p1],  S[U_EL + p1]);
            acc[mt][j][0] = 0.f; acc[mt][j][1] = 0.f;
            acc[mt][j][2] = 0.f; acc[mt][j][3] = 0.f;
        }

    // ========== Layer 2: enc1 @ W2  (8 K-tiles of 32) ==========
    for (int t = 0; t < 8; ++t) {
        const int cur = t & 1;
        const int bb  = U_B + cur * 8192;
        if (t < 7) {
            const int nb = U_B + (1 - cur) * 8192;
#pragma unroll
            for (int k = 0; k < 2; ++k) {
                int i = (tid + k * NT) * 4;
                CP16(sb4 + (nb + i) * 4,        g_W2Thi + (t + 1) * 4096 + i);
                CP16(sb4 + (nb + 4096 + i) * 4, g_W2Tlo + (t + 1) * 4096 + i);
            }
            CP_COMMIT();
            CP_WAIT1();
        } else {
            CP_WAIT0();
        }
        __syncthreads();
#pragma unroll
        for (int ks = 0; ks < 2; ++ks) {
            const int kb  = ks * 8 + kp;
            const int kbE = t * 16 + kb;
            uint32_t ah[2][4], al[2][4];
#pragma unroll
            for (int mt = 0; mt < 2; ++mt) {
                int r = (mrow + mt * 16) * LDE + kbE;
                ah[mt][0] = S[U_E + r];            ah[mt][1] = S[U_E + r + 8 * LDE];
                ah[mt][2] = S[U_E + r + 4];        ah[mt][3] = S[U_E + r + 8 * LDE + 4];
                al[mt][0] = S[U_EL + r];           al[mt][1] = S[U_EL + r + 8 * LDE];
                al[mt][2] = S[U_EL + r + 4];       al[mt][3] = S[U_EL + r + 8 * LDE + 4];
            }
            uint2 bhv[4], blv[4];
#pragma unroll
            for (int j = 0; j < 4; ++j) {
                int bi = bb + ks * 2048 + (wn * 32 + j * 8 + g) * 8 + 2 * kp;
                bhv[j] = *(const uint2*)&S[bi];
                blv[j] = *(const uint2*)&S[bi + 4096];
            }
#pragma unroll
            for (int mt = 0; mt < 2; ++mt)
#pragma unroll
                for (int j = 0; j < 4; ++j)
                    MMA_BF16(acc[mt][j], ah[mt], bhv[j].x, bhv[j].y);
#pragma unroll
            for (int mt = 0; mt < 2; ++mt)
#pragma unroll
                for (int j = 0; j < 4; ++j)
                    MMA_BF16(acc[mt][j], ah[mt], blv[j].x, blv[j].y);
#pragma unroll
            for (int mt = 0; mt < 2; ++mt)
#pragma unroll
                for (int j = 0; j < 4; ++j)
                    MMA_BF16(acc[mt][j], al[mt], bhv[j].x, bhv[j].y);
        }
        __syncthreads();
    }

    // stage Wq -> U_B region, overlap with epilogue 2
#pragma unroll
    for (int k = 0; k < 8; ++k) {
        int i = tid + k * NT;
        int comp = i >> 11, r = i & 2047;
        int n = r >> 5, c = r & 31;
        const uint32_t* gp = comp ? g_WqTlo : g_WqThi;
        CP16(sb4 + (U_B + comp * 8448 + n * LDE + c * 4) * 4, gp + n * 128 + c * 4);
    }
    CP_COMMIT();

    // epilogue 2: relu+bias -> sE in place
#pragma unroll
    for (int mt = 0; mt < 2; ++mt)
#pragma unroll
        for (int j = 0; j < 4; ++j) {
            int n = wn * 32 + j * 8 + 2 * kp;
            int r = mrow + mt * 16;
            float e0 = fmaxf(acc[mt][j][0] + sB2f[n],     0.f);
            float e1 = fmaxf(acc[mt][j][1] + sB2f[n + 1], 0.f);
            float e2 = fmaxf(acc[mt][j][2] + sB2f[n],     0.f);
            float e3 = fmaxf(acc[mt][j][3] + sB2f[n + 1], 0.f);
            int p0 = r * LDE + (n >> 1), p1 = p0 + 8 * LDE;
            split2(e0, e1, S[U_E + p0],  S[U_EL + p0]);
            split2(e2, e3, S[U_E + p1],  S[U_EL + p1]);
        }
    CP_WAIT0();
    __syncthreads();

    // ========== Layer 3: enc2 @ Wq  (K=256, N=8/warp) ==========
    float acc3[2][4];
#pragma unroll
    for (int mt = 0; mt < 2; ++mt)
#pragma unroll
        for (int q = 0; q < 4; ++q) acc3[mt][q] = 0.f;

#pragma unroll
    for (int ks = 0; ks < 16; ++ks) {
        const int kb = ks * 8 + kp;
        uint32_t ah[2][4], al[2][4];
#pragma unroll
        for (int mt = 0; mt < 2; ++mt) {
            int r = (mrow + mt * 16) * LDE + kb;
            ah[mt][0] = S[U_E + r];            ah[mt][1] = S[U_E + r + 8 * LDE];
            ah[mt][2] = S[U_E + r + 4];        ah[mt][3] = S[U_E + r + 8 * LDE + 4];
            al[mt][0] = S[U_EL + r];           al[mt][1] = S[U_EL + r + 8 * LDE];
            al[mt][2] = S[U_EL + r + 4];       al[mt][3] = S[U_EL + r + 8 * LDE + 4];
        }
        int bi = U_B + (wn * 8 + g) * LDE + kb;
        uint32_t bh0 = S[bi],        bh1 = S[bi + 4];
        uint32_t bl0 = S[bi + 8448], bl1 = S[bi + 8448 + 4];
#pragma unroll
        for (int mt = 0; mt < 2; ++mt) MMA_BF16(acc3[mt], ah[mt], bh0, bh1);
#pragma unroll
        for (int mt = 0; mt < 2; ++mt) MMA_BF16(acc3[mt], ah[mt], bl0, bl1);
#pragma unroll
        for (int mt = 0; mt < 2; ++mt) MMA_BF16(acc3[mt], al[mt], bh0, bh1);
    }

    // final: q = tanh(pre + bq); partial = sum q * Wh
    float part = 0.f;
#pragma unroll
    for (int mt = 0; mt < 2; ++mt) {
        int n = wn * 8 + 2 * kp;
        part = fmaf(tanhf(acc3[mt][0] + sBQf[n]),     sWHf[n],     part);
        part = fmaf(tanhf(acc3[mt][1] + sBQf[n + 1]), sWHf[n + 1], part);
        part = fmaf(tanhf(acc3[mt][2] + sBQf[n]),     sWHf[n],     part);
        part = fmaf(tanhf(acc3[mt][3] + sBQf[n + 1]), sWHf[n + 1], part);
    }

    __syncthreads();
    float* red = (float*)S;
    red[tid] = part;
    __syncthreads();
    for (int s = NT / 2; s > 0; s >>= 1) {
        if (tid < s) red[tid] += red[tid + s];
        __syncthreads();
    }

    __shared__ int s_last;
    if (tid == 0) {
        g_partial[blockIdx.x] = red[0];
        __threadfence();
        unsigned v = atomicAdd(&g_count, 1u);
        s_last = (v == GRID_F - 1) ? 1 : 0;
    }
    __syncthreads();
    if (s_last) {
        if (tid < GRID_F)
            red[tid] = ((const volatile float*)g_partial)[tid];
        __syncthreads();
        for (int s = GRID_F / 2; s > 0; s >>= 1) {
            if (tid < s) red[tid] += red[tid + s];
            __syncthreads();
        }
        if (tid == 0) out[0] = red[0] + bh[0];
    }
}

extern "C" void kernel_launch(void* const* d_in, const int* in_sizes, int n_in,
                              void* d_out, int out_size)
{
    const float* X  = (const float*)d_in[0];
    const float* W1 = (const float*)d_in[1];
    const float* b1 = (const float*)d_in[2];
    const float* W2 = (const float*)d_in[3];
    const float* b2 = (const float*)d_in[4];
    const float* Wq = (const float*)d_in[5];
    const float* bq = (const float*)d_in[6];
    const float* Wh = (const float*)d_in[7];
    const float* bh = (const float*)d_in[8];
    float* out = (float*)d_out;

    cudaFuncSetAttribute(main_kernel,
                         cudaFuncAttributeMaxDynamicSharedMemorySize, SMEM_BYTES);

    prep_kernel<<<PREP_GRID, PNT>>>(W1, W2, Wq);
    main_kernel<<<GRID_F, NT, SMEM_BYTES>>>(X, b1, b2, bq, Wh, bh, out);
}